// round 6
// baseline (speedup 1.0000x reference)
#include <cuda_runtime.h>
#include <cuda_bf16.h>
#include <cstdint>

// Problem constants (fixed by the dataset)
#define CLASSES   128
#define M_IN      64      // inner dim (K)
#define N_OUT     32      // outputs per class
#define SPLIT     2       // blocks per class in main kernel
#define MAIN_THREADS  256 // 8 warps
#define HIST_THREADS  1024
#define MAX_HIST_BLOCKS 1024
#define WT_STRIDE 36      // padded row stride (floats), 16B-aligned

// packed fp32x2 ops (sm_103a; only reachable via PTX)
#define FMA2(d, a, b, c) \
    asm("fma.rn.f32x2 %0, %1, %2, %3;" : "=l"(d) : "l"(a), "l"(b), "l"(c))
#define ADD2(d, a, b) \
    asm("add.rn.f32x2 %0, %1, %2;" : "=l"(d) : "l"(a), "l"(b))
#define PACKDUP(d, f) \
    asm("mov.b64 %0, {%1, %1};" : "=l"(d) : "f"(f))

// ---------------- scratch (no allocations allowed) ----------------
__device__ int g_offsets[CLASSES + 1];
__device__ int g_cursor[CLASSES];
__device__ int g_perm[1 << 20];           // supports up to 1M samples
__device__ int g_blockcounts[MAX_HIST_BLOCKS * CLASSES];

// Detect whether the index buffer is int64 or int32.
// If int64 with small class values, every odd int32 word (LE high half) is 0.
__device__ __forceinline__ void detect_is64(const int* w, int nwords, int tid,
                                            int* flag) {
    if (tid < 32) {
        int idx = 2 * tid + 1;
        int v = (idx < nwords) ? w[idx] : 0;
        unsigned nz = __ballot_sync(0xFFFFFFFFu, v != 0);
        if (tid == 0) *flag = (nz == 0u) ? 1 : 0;
    }
}

__device__ __forceinline__ int load_class(const void* inds, int n, int is64) {
    int c;
    if (is64) c = (int)((const long long*)inds)[n];
    else      c = ((const int*)inds)[n];
    return c & (CLASSES - 1);   // defensive clamp
}

// ---------------- kernel 1: per-block histogram ----------------
__global__ void hist_kernel(const void* __restrict__ inds, int N) {
    __shared__ int s_cnt[CLASSES];
    __shared__ int s_is64;
    int t = threadIdx.x;
    if (t < CLASSES) s_cnt[t] = 0;
    detect_is64((const int*)inds, N, t, &s_is64);
    __syncthreads();
    int n = blockIdx.x * HIST_THREADS + t;
    if (n < N) atomicAdd(&s_cnt[load_class(inds, n, s_is64)], 1);
    __syncthreads();
    if (t < CLASSES) g_blockcounts[blockIdx.x * CLASSES + t] = s_cnt[t];
}

// ---------------- kernel 2: reduce + exclusive scan ----------------
__global__ void scan_kernel(int nblocks) {
    __shared__ int s[CLASSES];
    int t = threadIdx.x;   // 128 threads
    int sum = 0;
    for (int b = 0; b < nblocks; b++)
        sum += g_blockcounts[b * CLASSES + t];
    s[t] = sum;
    __syncthreads();
    #pragma unroll
    for (int off = 1; off < CLASSES; off <<= 1) {
        int v = (t >= off) ? s[t - off] : 0;
        __syncthreads();
        s[t] += v;
        __syncthreads();
    }
    int incl = s[t];
    g_offsets[t + 1] = incl;
    if (t == 0) g_offsets[0] = 0;
    g_cursor[t] = incl - sum;   // exclusive prefix
}

// ---------------- kernel 3: scatter (two-level) ----------------
__global__ void scatter_kernel(const void* __restrict__ inds, int N) {
    __shared__ int s_cnt[CLASSES];
    __shared__ int s_base[CLASSES];
    __shared__ int s_is64;
    int t = threadIdx.x;
    if (t < CLASSES) s_cnt[t] = 0;
    detect_is64((const int*)inds, N, t, &s_is64);
    __syncthreads();
    int n = blockIdx.x * HIST_THREADS + t;
    int c = 0, loc = 0;
    if (n < N) {
        c = load_class(inds, n, s_is64);
        loc = atomicAdd(&s_cnt[c], 1);
    }
    __syncthreads();
    if (t < CLASSES) s_base[t] = atomicAdd(&g_cursor[t], s_cnt[t]);
    __syncthreads();
    if (n < N) g_perm[s_base[c] + loc] = n;
}

// ---------------- kernel 4: main gathered GEMV (sample-per-lane) ----------
// grid = CLASSES * SPLIT blocks, 256 threads (8 warps), 2 CTAs/SM.
// Lane owns ONE sample per pass. x row streams through a 2-deep ping-pong of
// 4xfloat4 register chunks (16 k-values each); W^T broadcast from shared;
// 32 outputs live in 16 packed f32x2 accumulators. Peak live regs ~90.
__global__ void __launch_bounds__(MAIN_THREADS, 2)
main_kernel(const float* __restrict__ x,
            const float* __restrict__ W,
            const float* __restrict__ b,
            float* __restrict__ out) {
    __shared__ float Wt_sh[M_IN][WT_STRIDE];        // [k][j], padded
    __shared__ unsigned long long b_pk[N_OUT / 2];  // packed bias pairs

    const int tid  = threadIdx.x;
    const int w    = tid >> 5;
    const int lane = tid & 31;

    const int c = blockIdx.x / SPLIT;
    const int q = blockIdx.x % SPLIT;

    // longest chain first: offsets -> perm -> x
    const int start = g_offsets[c];
    const int endc  = g_offsets[c + 1];

    // stage W transposed (coalesced global reads) + packed bias
    const float* Wc = W + (size_t)c * (N_OUT * M_IN);   // [j][k] row-major
    #pragma unroll
    for (int i = 0; i < 8; i++) {
        int idx = tid + i * MAIN_THREADS;               // 0..2047
        Wt_sh[idx & 63][idx >> 6] = Wc[idx];            // Wt[k][j] = W[j][k]
    }
    if (tid < N_OUT / 2)
        b_pk[tid] = ((const unsigned long long*)(b + c * N_OUT))[tid];

    const int total = endc - start;
    const int chunk = (total + SPLIT - 1) / SPLIT;
    const int s0 = start + q * chunk;
    const int s1 = min(endc, s0 + chunk);

    int base = s0 + w * 32;

    // prefetch pass-0 sample id + first x chunk BEFORE the barrier
    int n0 = 0;
    float4 xa[4], xb[4];
    if (base < s1) {
        int i0 = base + lane;
        n0 = g_perm[(i0 < s1) ? i0 : (s1 - 1)];
        const float4* xp = reinterpret_cast<const float4*>(x + (size_t)n0 * M_IN);
        #pragma unroll
        for (int i = 0; i < 4; i++) xa[i] = xp[i];      // k 0..15
    }
    __syncthreads();

    for (; base < s1; base += 8 * 32) {
        const bool valid = (base + lane) < s1;
        const int n = n0;
        const int nbase = base + 8 * 32;
        const float4* xp = reinterpret_cast<const float4*>(x + (size_t)n * M_IN);

        // prefetch next pass's sample id early
        int nn = 0;
        if (nbase < s1) {
            int i1 = nbase + lane;
            nn = g_perm[(i1 < s1) ? i1 : (s1 - 1)];
        }

        unsigned long long acc[16];
        #pragma unroll
        for (int p = 0; p < 16; p++) acc[p] = 0ull;

        // compute one 16-k chunk from xreg
        #define COMPUTE_CHUNK(CH, XREG)                                         \
        do {                                                                    \
            _Pragma("unroll")                                                   \
            for (int k4 = 0; k4 < 4; k4++) {                                    \
                const float4 xv = XREG[k4];                                     \
                _Pragma("unroll")                                               \
                for (int e = 0; e < 4; e++) {                                   \
                    const int k = (CH) * 16 + k4 * 4 + e;                       \
                    float xs = (e == 0) ? xv.x : (e == 1) ? xv.y                \
                             : (e == 2) ? xv.z : xv.w;                          \
                    unsigned long long xp2;                                     \
                    PACKDUP(xp2, xs);                                           \
                    const ulonglong2* wk =                                      \
                        reinterpret_cast<const ulonglong2*>(&Wt_sh[k][0]);      \
                    _Pragma("unroll")                                           \
                    for (int j4 = 0; j4 < 8; j4++) {                            \
                        ulonglong2 wv = wk[j4];      /* broadcast LDS.128 */    \
                        FMA2(acc[2 * j4],     wv.x, xp2, acc[2 * j4]);          \
                        FMA2(acc[2 * j4 + 1], wv.y, xp2, acc[2 * j4 + 1]);      \
                    }                                                           \
                }                                                               \
            }                                                                   \
        } while (0)

        // ping-pong pipeline: xa holds chunk0 on entry
        #pragma unroll
        for (int i = 0; i < 4; i++) xb[i] = xp[4 + i];  // chunk1 in flight
        COMPUTE_CHUNK(0, xa);
        #pragma unroll
        for (int i = 0; i < 4; i++) xa[i] = xp[8 + i];  // chunk2 in flight
        COMPUTE_CHUNK(1, xb);
        #pragma unroll
        for (int i = 0; i < 4; i++) xb[i] = xp[12 + i]; // chunk3 in flight
        COMPUTE_CHUNK(2, xa);
        if (nbase < s1) {                               // next sample chunk0
            const float4* xq =
                reinterpret_cast<const float4*>(x + (size_t)nn * M_IN);
            #pragma unroll
            for (int i = 0; i < 4; i++) xa[i] = xq[i];
        }
        COMPUTE_CHUNK(3, xb);
        #undef COMPUTE_CHUNK

        // bias + store: packed f32x2 bits == two consecutive floats
        if (valid) {
            float* orow = out + (size_t)n * N_OUT;
            #pragma unroll
            for (int p = 0; p < 16; p++) { ADD2(acc[p], acc[p], b_pk[p]); }
            #pragma unroll
            for (int qd = 0; qd < 8; qd++) {
                ulonglong2 st;
                st.x = acc[2 * qd];
                st.y = acc[2 * qd + 1];
                *reinterpret_cast<ulonglong2*>(orow + 4 * qd) = st;
            }
        }
        n0 = nn;
    }
}

// ---------------- launch ----------------
extern "C" void kernel_launch(void* const* d_in, const int* in_sizes, int n_in,
                              void* d_out, int out_size) {
    const float* x    = (const float*)d_in[0];
    const void*  inds = d_in[1];
    const float* W    = (const float*)d_in[2];
    const float* b    = (const float*)d_in[3];
    float*       out  = (float*)d_out;
    const int N = in_sizes[1];

    int hist_blocks = (N + HIST_THREADS - 1) / HIST_THREADS;
    if (hist_blocks > MAX_HIST_BLOCKS) hist_blocks = MAX_HIST_BLOCKS;
    hist_kernel<<<hist_blocks, HIST_THREADS>>>(inds, N);
    scan_kernel<<<1, CLASSES>>>(hist_blocks);
    scatter_kernel<<<hist_blocks, HIST_THREADS>>>(inds, N);
    main_kernel<<<CLASSES * SPLIT, MAIN_THREADS>>>(x, W, b, out);
}